// round 1
// baseline (speedup 1.0000x reference)
#include <cuda_runtime.h>
#include <math.h>

#define NNODES 100000
#define DIM 256
#define NHEAD 8
#define HDIM 32
#define NEDGE 300000
#define NB 25600000ull   // NNODES * DIM floats per slab

// Slab layout in g_buf:
// 0:Kp 1:Qp 2:Vp 3:Ka 4:Qa 5:Va 6:qRw 7:qRc 8:qRwb 9:accp 10:acca
// qRw/qRc reused as pre-LN temporaries for paper/author after edge phase.
__device__ float g_buf[11ull * NB];
__device__ float g_norm[2 * NNODES];

// ---------------------------------------------------------------------------
// Zero accumulators + norms
// ---------------------------------------------------------------------------
__global__ void zero_kernel(float* __restrict__ acc2, float* __restrict__ nrm) {
    size_t i = (size_t)blockIdx.x * blockDim.x + threadIdx.x;
    if (i < 2ull * NB) acc2[i] = 0.0f;
    if (i < 2 * NNODES) nrm[i] = 0.0f;
}

// ---------------------------------------------------------------------------
// fp32 GEMM: C[M,256] = A[M,256] @ W[256,256] + bias (+ res). BM=128 BN=64 BK=16
// ---------------------------------------------------------------------------
template <bool RES>
__global__ void __launch_bounds__(256) gemm256(
    const float* __restrict__ A, const float* __restrict__ W,
    const float* __restrict__ bias, const float* __restrict__ res,
    float* __restrict__ C, int M)
{
    __shared__ float As[16][132];   // transposed A tile, padded
    __shared__ float Bs[16][64];

    const int tid = threadIdx.x;
    const int bm = blockIdx.x * 128;
    const int bn = blockIdx.y * 64;
    const int tx = tid & 15;   // 0..15 -> 4 cols each
    const int ty = tid >> 4;   // 0..15 -> 8 rows each

    float acc[8][4];
#pragma unroll
    for (int i = 0; i < 8; i++)
#pragma unroll
        for (int j = 0; j < 4; j++) acc[i][j] = 0.0f;

    const int arow0 = tid >> 2;   // 0..63
    const int ac4 = tid & 3;      // float4 index within 16-wide K slice
    const int brow = tid >> 4;    // 0..15
    const int bc4 = tid & 15;     // 0..15

    for (int kk = 0; kk < 256; kk += 16) {
        // Load A tile (128x16), store transposed
#pragma unroll
        for (int half = 0; half < 2; half++) {
            int row = arow0 + half * 64;
            int grow = bm + row;
            float4 v = make_float4(0.f, 0.f, 0.f, 0.f);
            if (grow < M)
                v = *(const float4*)&A[(size_t)grow * 256 + kk + ac4 * 4];
            As[ac4 * 4 + 0][row] = v.x;
            As[ac4 * 4 + 1][row] = v.y;
            As[ac4 * 4 + 2][row] = v.z;
            As[ac4 * 4 + 3][row] = v.w;
        }
        // Load B tile (16x64)
        {
            float4 v = *(const float4*)&W[(size_t)(kk + brow) * 256 + bn + bc4 * 4];
            *(float4*)&Bs[brow][bc4 * 4] = v;
        }
        __syncthreads();

#pragma unroll
        for (int k = 0; k < 16; k++) {
            float4 b = *(float4*)&Bs[k][tx * 4];
            float a[8];
            *(float4*)&a[0] = *(float4*)&As[k][ty * 8];
            *(float4*)&a[4] = *(float4*)&As[k][ty * 8 + 4];
#pragma unroll
            for (int i = 0; i < 8; i++) {
                acc[i][0] += a[i] * b.x;
                acc[i][1] += a[i] * b.y;
                acc[i][2] += a[i] * b.z;
                acc[i][3] += a[i] * b.w;
            }
        }
        __syncthreads();
    }

    float4 bb = *(const float4*)&bias[bn + tx * 4];
#pragma unroll
    for (int i = 0; i < 8; i++) {
        int grow = bm + ty * 8 + i;
        if (grow < M) {
            float4 o;
            o.x = acc[i][0] + bb.x;
            o.y = acc[i][1] + bb.y;
            o.z = acc[i][2] + bb.z;
            o.w = acc[i][3] + bb.w;
            if (RES) {
                float4 r = *(const float4*)&res[(size_t)grow * 256 + bn + tx * 4];
                o.x += r.x; o.y += r.y; o.z += r.z; o.w += r.w;
            }
            *(float4*)&C[(size_t)grow * 256 + bn + tx * 4] = o;
        }
    }
}

// ---------------------------------------------------------------------------
// qR precompute: out[n,h,f] = sum_d Q[n,h,d] * R[h,d,f].  32 nodes per block.
// ---------------------------------------------------------------------------
__global__ void __launch_bounds__(256) qr_kernel(
    const float* __restrict__ Q, const float* __restrict__ R,
    float* __restrict__ out)
{
    __shared__ float Rs[8192];   // 8*32*32
    __shared__ float Qs[256];
    const int tid = threadIdx.x;
    for (int i = tid; i < 8192; i += 256) Rs[i] = R[i];

    const int h = tid >> 5;
    const int f = tid & 31;
    const float* Rh = &Rs[h * 1024];

    for (int nl = 0; nl < 32; nl++) {
        int node = blockIdx.x * 32 + nl;
        __syncthreads();
        Qs[tid] = Q[(size_t)node * 256 + tid];
        __syncthreads();
        float t = 0.0f;
#pragma unroll
        for (int d = 0; d < 32; d++)
            t += Qs[h * 32 + d] * Rh[d * 32 + f];
        out[(size_t)node * 256 + tid] = t;
    }
}

// ---------------------------------------------------------------------------
// Edge kernel: one warp per edge; score = <qR[dst], K[src]> per head,
// aexp = exp(clip(score/sqrt(32))), scatter v*aexp and mean(aexp).
// ---------------------------------------------------------------------------
__global__ void __launch_bounds__(256) edge_kernel(
    const float* __restrict__ qR, const float* __restrict__ Ksrc,
    const float* __restrict__ Vsrc, const int* __restrict__ ei,
    float* __restrict__ accum, float* __restrict__ nrm)
{
    const int lane = threadIdx.x & 31;
    const int warp = (blockIdx.x * blockDim.x + threadIdx.x) >> 5;
    const int nwarps = (gridDim.x * blockDim.x) >> 5;

    for (int e = warp; e < NEDGE; e += nwarps) {
        int src = ei[e];
        int dst = ei[NEDGE + e];
        const float* qrow = qR + (size_t)dst * 256;
        const float* krow = Ksrc + (size_t)src * 256;

        float aexp[NHEAD];
        float asum = 0.0f;
#pragma unroll
        for (int h = 0; h < NHEAD; h++) {
            float p = qrow[h * 32 + lane] * krow[h * 32 + lane];
#pragma unroll
            for (int o = 16; o; o >>= 1)
                p += __shfl_xor_sync(0xffffffffu, p, o);
            float s = p * 0.17677669529663687f;   // 1/sqrt(32)
            s = fminf(fmaxf(s, -5.0f), 5.0f);
            float a = expf(s);
            aexp[h] = a;
            asum += a;
        }

        const float* vrow = Vsrc + (size_t)src * 256;
        float* arow = accum + (size_t)dst * 256;
#pragma unroll
        for (int h = 0; h < NHEAD; h++)
            atomicAdd(&arow[h * 32 + lane], vrow[h * 32 + lane] * aexp[h]);

        if (lane == 0)
            atomicAdd(&nrm[dst], asum * 0.125f);
    }
}

// ---------------------------------------------------------------------------
// agg = accum / max(norm, 1e-8)
// ---------------------------------------------------------------------------
__global__ void div_kernel(float* __restrict__ accum, const float* __restrict__ nrm) {
    size_t i = (size_t)blockIdx.x * blockDim.x + threadIdx.x;
    if (i < NB)
        accum[i] = accum[i] / fmaxf(nrm[i >> 8], 1e-8f);
}

// ---------------------------------------------------------------------------
// LayerNorm (biased var) per row of 256; one warp per row.
// ---------------------------------------------------------------------------
__global__ void __launch_bounds__(256) ln_kernel(
    const float* __restrict__ in, const float* __restrict__ g,
    const float* __restrict__ be, float* __restrict__ out)
{
    const int warp = (blockIdx.x * blockDim.x + threadIdx.x) >> 5;
    const int lane = threadIdx.x & 31;
    if (warp >= NNODES) return;

    const float* row = in + (size_t)warp * 256;
    float v[8];
    float s = 0.0f;
#pragma unroll
    for (int j = 0; j < 8; j++) {
        v[j] = row[lane + j * 32];
        s += v[j];
    }
#pragma unroll
    for (int o = 16; o; o >>= 1) s += __shfl_xor_sync(0xffffffffu, s, o);
    float m = s * (1.0f / 256.0f);

    float q = 0.0f;
#pragma unroll
    for (int j = 0; j < 8; j++) {
        float d = v[j] - m;
        q += d * d;
    }
#pragma unroll
    for (int o = 16; o; o >>= 1) q += __shfl_xor_sync(0xffffffffu, q, o);
    float rstd = rsqrtf(q * (1.0f / 256.0f) + 1e-5f);

    float* orow = out + (size_t)warp * 256;
#pragma unroll
    for (int j = 0; j < 8; j++) {
        int c = lane + j * 32;
        orow[c] = (v[j] - m) * rstd * g[c] + be[c];
    }
}

// ---------------------------------------------------------------------------
extern "C" void kernel_launch(void* const* d_in, const int* in_sizes, int n_in,
                              void* d_out, int out_size) {
    const float* x_p   = (const float*)d_in[0];
    const float* x_a   = (const float*)d_in[1];
    const float* Wk_p  = (const float*)d_in[2];
    const float* bk_p  = (const float*)d_in[3];
    const float* Wq_p  = (const float*)d_in[4];
    const float* bq_p  = (const float*)d_in[5];
    const float* Wv_p  = (const float*)d_in[6];
    const float* bv_p  = (const float*)d_in[7];
    const float* Wo_p  = (const float*)d_in[8];
    const float* bo_p  = (const float*)d_in[9];
    const float* g_p   = (const float*)d_in[10];
    const float* be_p  = (const float*)d_in[11];
    const float* Wk_a  = (const float*)d_in[12];
    const float* bk_a  = (const float*)d_in[13];
    const float* Wq_a  = (const float*)d_in[14];
    const float* bq_a  = (const float*)d_in[15];
    const float* Wv_a  = (const float*)d_in[16];
    const float* bv_a  = (const float*)d_in[17];
    const float* Wo_a  = (const float*)d_in[18];
    const float* bo_a  = (const float*)d_in[19];
    const float* g_a   = (const float*)d_in[20];
    const float* be_a  = (const float*)d_in[21];
    const float* R_w   = (const float*)d_in[22];
    const int*   ei_w  = (const int*)d_in[23];
    const float* R_c   = (const float*)d_in[24];
    const int*   ei_c  = (const int*)d_in[25];
    const float* R_wb  = (const float*)d_in[26];
    const int*   ei_wb = (const int*)d_in[27];
    float* out = (float*)d_out;

    float* buf = nullptr;
    float* nrm = nullptr;
    cudaGetSymbolAddress((void**)&buf, g_buf);
    cudaGetSymbolAddress((void**)&nrm, g_norm);

    float* Kp   = buf + 0 * NB;
    float* Qp   = buf + 1 * NB;
    float* Vp   = buf + 2 * NB;
    float* Ka   = buf + 3 * NB;
    float* Qa   = buf + 4 * NB;
    float* Va   = buf + 5 * NB;
    float* qRw  = buf + 6 * NB;
    float* qRc  = buf + 7 * NB;
    float* qRwb = buf + 8 * NB;
    float* accp = buf + 9 * NB;
    float* acca = buf + 10 * NB;
    float* np_  = nrm;
    float* na_  = nrm + NNODES;

    // 1) zero accumulators (accp, acca contiguous) + norms
    zero_kernel<<<200000, 256>>>(accp, nrm);

    // 2) KQV projections
    dim3 ggrid((NNODES + 127) / 128, 4);
    gemm256<false><<<ggrid, 256>>>(x_p, Wk_p, bk_p, nullptr, Kp, NNODES);
    gemm256<false><<<ggrid, 256>>>(x_p, Wq_p, bq_p, nullptr, Qp, NNODES);
    gemm256<false><<<ggrid, 256>>>(x_p, Wv_p, bv_p, nullptr, Vp, NNODES);
    gemm256<false><<<ggrid, 256>>>(x_a, Wk_a, bk_a, nullptr, Ka, NNODES);
    gemm256<false><<<ggrid, 256>>>(x_a, Wq_a, bq_a, nullptr, Qa, NNODES);
    gemm256<false><<<ggrid, 256>>>(x_a, Wv_a, bv_a, nullptr, Va, NNODES);

    // 3) qR = Q @ R per relation (dst-side Q)
    qr_kernel<<<NNODES / 32, 256>>>(Qp, R_w,  qRw);   // writes:    dst=paper
    qr_kernel<<<NNODES / 32, 256>>>(Qp, R_c,  qRc);   // cites:     dst=paper
    qr_kernel<<<NNODES / 32, 256>>>(Qa, R_wb, qRwb);  // writtenby: dst=author

    // 4) edge message passing
    edge_kernel<<<2048, 256>>>(qRw,  Ka, Va, ei_w,  accp, np_);  // author->paper
    edge_kernel<<<2048, 256>>>(qRc,  Kp, Vp, ei_c,  accp, np_);  // paper->paper
    edge_kernel<<<2048, 256>>>(qRwb, Kp, Vp, ei_wb, acca, na_);  // paper->author

    // 5) normalize aggregates
    div_kernel<<<(int)((NB + 255) / 256), 256>>>(accp, np_);
    div_kernel<<<(int)((NB + 255) / 256), 256>>>(acca, na_);

    // 6) output projection + residual (into recycled qR slabs)
    gemm256<true><<<ggrid, 256>>>(accp, Wo_p, bo_p, x_p, qRw, NNODES);
    gemm256<true><<<ggrid, 256>>>(acca, Wo_a, bo_a, x_a, qRc, NNODES);

    // 7) layernorm -> output [2, N, 256]
    ln_kernel<<<(NNODES * 32 + 255) / 256, 256>>>(qRw, g_p, be_p, out);
    ln_kernel<<<(NNODES * 32 + 255) / 256, 256>>>(qRc, g_a, be_a, out + (size_t)NNODES * 256);
}

// round 3
// speedup vs baseline: 1.4696x; 1.4696x over previous
#include <cuda_runtime.h>
#include <cuda_bf16.h>
#include <math.h>
#include <stdint.h>

#define NNODES 100000
#define NEDGE 300000
#define NHEAD 8
#define NB 25600000ull   // NNODES * 256 floats per slab

// fp32 slabs: 0:Kp 1:Vp 2:Ka 3:Va 4:qRw 5:qRc 6:qRwb 7:accp 8:acca
// slabs 4,5 recycled as pre-LN temporaries after edge phase.
__device__ float g_buf[9ull * NB];
__device__ float g_norm[2 * NNODES];
__device__ __nv_bfloat16 g_acat[2ull * NNODES * 512];   // [hi(256)|lo(256)] per row
__device__ __nv_bfloat16 g_bcat[9ull * 256 * 768];      // [n][hi|lo|hi] k-contiguous
__device__ float g_bias[3 * 256];                        // composed qR biases

// ---------------------------------------------------------------------------
// PTX helpers
// ---------------------------------------------------------------------------
static __device__ __forceinline__ uint32_t s2u(const void* p) {
    uint32_t a;
    asm("{ .reg .u64 t; cvta.to.shared.u64 t, %1; cvt.u32.u64 %0, t; }" : "=r"(a) : "l"(p));
    return a;
}
static __device__ __forceinline__ void cpa16(uint32_t dst, const void* src, int sz) {
    asm volatile("cp.async.cg.shared.global [%0], [%1], 16, %2;"
                 :: "r"(dst), "l"(src), "r"(sz) : "memory");
}
#define CP_COMMIT() asm volatile("cp.async.commit_group;" ::: "memory")
#define CP_WAIT1()  asm volatile("cp.async.wait_group 1;" ::: "memory")

#define LDM4(r, addr) \
    asm volatile("ldmatrix.sync.aligned.m8n8.x4.shared.b16 {%0,%1,%2,%3}, [%4];" \
                 : "=r"((r)[0]), "=r"((r)[1]), "=r"((r)[2]), "=r"((r)[3]) : "r"(addr))

#define MMA16816(c, a, b0, b1) \
    asm volatile("mma.sync.aligned.m16n8k16.row.col.f32.bf16.bf16.f32 " \
                 "{%0,%1,%2,%3}, {%4,%5,%6,%7}, {%8,%9}, {%0,%1,%2,%3};" \
                 : "+f"((c)[0]), "+f"((c)[1]), "+f"((c)[2]), "+f"((c)[3]) \
                 : "r"((a)[0]), "r"((a)[1]), "r"((a)[2]), "r"((a)[3]), "r"(b0), "r"(b1))

#define STAGE_B 20480u   // A tile (10240) + B tile (10240), 80B-pitch rows
#define GEMM_SMEM (3 * 20480)

// ---------------------------------------------------------------------------
// HMMA split-bf16 GEMM: C[M,256] = A[M,256]@W[256,256] + bias (+res)
// A: [M,512] bf16 (hi|lo). B: [256 n][768 k] bf16 (Whi|Wlo|Whi, k-contig).
// K schedule: 24 chunks of 32: c0-7 Ahi*Bhi, c8-15 Ahi*Blo, c16-23 Alo*Bhi.
// BM=128 BN=128 BK=32, 8 warps (4x2), warp tile 32x64, 3-stage cp.async.
// ---------------------------------------------------------------------------
template <bool RES>
__global__ void __launch_bounds__(256) gemm_tc(
    const __nv_bfloat16* __restrict__ A, const __nv_bfloat16* __restrict__ B,
    const float* __restrict__ bias, const float* __restrict__ res,
    float* __restrict__ C, int M)
{
    extern __shared__ __align__(16) uint8_t smem[];
    const uint32_t sbase = s2u(smem);
    const int tid = threadIdx.x;
    const int lane = tid & 31;
    const int wid = tid >> 5;
    const int wm = wid & 3;          // 4 warps along M
    const int wn = wid >> 2;         // 2 warps along N
    const int bm = blockIdx.x * 128;
    const int bn = blockIdx.y * 128;

    float acc[2][8][4];
#pragma unroll
    for (int i = 0; i < 2; i++)
#pragma unroll
        for (int j = 0; j < 8; j++)
#pragma unroll
            for (int q = 0; q < 4; q++) acc[i][j][q] = 0.0f;

    const int lrow = tid >> 2;   // 0..63
    const int lch = tid & 3;     // 16B chunk within 64B row

    // ldmatrix source offsets (within a stage's A/B tile)
    const uint32_t aoffs = (uint32_t)((wm * 32 + (lane & 15)) * 80 + (lane >> 4) * 16);
    const uint32_t boffs = (uint32_t)((wn * 64 + (lane & 7) + ((lane >> 4) << 3)) * 80
                                      + ((lane >> 3) & 1) * 16);

#define LOAD_TILE(c, st) do {                                                   \
        uint32_t sA_ = sbase + (uint32_t)(st) * STAGE_B;                        \
        uint32_t sB_ = sA_ + 10240u;                                            \
        int aoff_ = ((c) < 16) ? (((c) & 7) * 32) : (256 + ((c) - 16) * 32);    \
        int boff_ = (c) * 32;                                                   \
        _Pragma("unroll")                                                       \
        for (int i_ = 0; i_ < 2; i_++) {                                        \
            int row_ = lrow + i_ * 64;                                          \
            int grow_ = bm + row_;                                              \
            int cg_ = grow_ < M ? grow_ : (M - 1);                              \
            cpa16(sA_ + row_ * 80 + lch * 16,                                   \
                  (const uint8_t*)A + ((size_t)cg_ * 512 + aoff_ + lch * 8) * 2,\
                  grow_ < M ? 16 : 0);                                          \
            cpa16(sB_ + row_ * 80 + lch * 16,                                   \
                  (const uint8_t*)B + ((size_t)(bn + row_) * 768 + boff_ + lch * 8) * 2, \
                  16);                                                          \
        }                                                                       \
    } while (0)

    LOAD_TILE(0, 0); CP_COMMIT();
    LOAD_TILE(1, 1); CP_COMMIT();

    for (int c = 0; c < 24; c++) {
        CP_WAIT1();
        __syncthreads();
        int nc = c + 2;
        if (nc < 24) LOAD_TILE(nc, nc % 3);
        CP_COMMIT();

        uint32_t sA = sbase + (uint32_t)(c % 3) * STAGE_B;
        uint32_t sB = sA + 10240u;
#pragma unroll
        for (int ks = 0; ks < 2; ks++) {
            uint32_t a[2][4];
            LDM4(a[0], sA + aoffs + ks * 32);
            LDM4(a[1], sA + aoffs + 1280 + ks * 32);
            uint32_t b[4][4];
#pragma unroll
            for (int nj = 0; nj < 4; nj++)
                LDM4(b[nj], sB + boffs + nj * 1280 + ks * 32);
#pragma unroll
            for (int mi = 0; mi < 2; mi++)
#pragma unroll
                for (int nj = 0; nj < 4; nj++) {
                    MMA16816(acc[mi][nj * 2 + 0], a[mi], b[nj][0], b[nj][1]);
                    MMA16816(acc[mi][nj * 2 + 1], a[mi], b[nj][2], b[nj][3]);
                }
        }
        __syncthreads();
    }

    // Epilogue
#pragma unroll
    for (int mi = 0; mi < 2; mi++) {
        int r0 = bm + wm * 32 + mi * 16 + (lane >> 2);
#pragma unroll
        for (int half = 0; half < 2; half++) {
            int row = r0 + half * 8;
            if (row < M) {
#pragma unroll
                for (int nj = 0; nj < 8; nj++) {
                    int col = bn + wn * 64 + nj * 8 + (lane & 3) * 2;
                    float v0 = acc[mi][nj][half * 2 + 0] + bias[col];
                    float v1 = acc[mi][nj][half * 2 + 1] + bias[col + 1];
                    if (RES) {
                        const float* rp = res + (size_t)row * 256 + col;
                        v0 += rp[0]; v1 += rp[1];
                    }
                    float2* dst = (float2*)(C + (size_t)row * 256 + col);
                    *dst = make_float2(v0, v1);
                }
            }
        }
    }
#undef LOAD_TILE
}

// ---------------------------------------------------------------------------
// Prep: plain weight W[256k][256n] fp32 -> Bcat[n][hi|lo|hi] bf16
// ---------------------------------------------------------------------------
__global__ void prep_w(const float* __restrict__ W, __nv_bfloat16* __restrict__ Bc) {
    int n = blockIdx.x, k = threadIdx.x;
    float w = W[k * 256 + n];
    __nv_bfloat16 hi = __float2bfloat16(w);
    __nv_bfloat16 lo = __float2bfloat16(w - __bfloat162float(hi));
    Bc[(size_t)n * 768 + k] = hi;
    Bc[(size_t)n * 768 + 256 + k] = lo;
    Bc[(size_t)n * 768 + 512 + k] = hi;
}

// ---------------------------------------------------------------------------
// Prep: composed qR weight W'[i][h*32+f] = sum_d Wq[i][h*32+d]*R[h][d][f],
// b'[h*32+f] = sum_d bq[h*32+d]*R[h][d][f]. Split to Bcat + fp32 bias.
// ---------------------------------------------------------------------------
__global__ void __launch_bounds__(256) prep_qr(
    const float* __restrict__ Wq, const float* __restrict__ bq,
    const float* __restrict__ R, __nv_bfloat16* __restrict__ Bc,
    float* __restrict__ bprime)
{
    __shared__ float Rs[8192];
    int tid = threadIdx.x;
    for (int i = tid; i < 8192; i += 256) Rs[i] = R[i];
    __syncthreads();

    int i = blockIdx.x;  // 0..255 weight rows, 256 = bias
    int h = tid >> 5, f = tid & 31;
    const float* src = (i < 256) ? &Wq[i * 256] : bq;
    float t = 0.0f;
#pragma unroll
    for (int d = 0; d < 32; d++)
        t += src[h * 32 + d] * Rs[h * 1024 + d * 32 + f];
    if (i < 256) {
        __nv_bfloat16 hi = __float2bfloat16(t);
        __nv_bfloat16 lo = __float2bfloat16(t - __bfloat162float(hi));
        Bc[(size_t)tid * 768 + i] = hi;
        Bc[(size_t)tid * 768 + 256 + i] = lo;
        Bc[(size_t)tid * 768 + 512 + i] = hi;
    } else {
        bprime[tid] = t;
    }
}

// ---------------------------------------------------------------------------
// Split fp32 [M,256] -> bf16 [M, hi(256)|lo(256)]
// ---------------------------------------------------------------------------
__global__ void split_x(const float* __restrict__ x, __nv_bfloat16* __restrict__ A) {
    size_t i = (size_t)blockIdx.x * 256 + threadIdx.x;
    float v = x[i];
    int row = (int)(i >> 8), col = (int)(i & 255);
    __nv_bfloat16 hi = __float2bfloat16(v);
    __nv_bfloat16 lo = __float2bfloat16(v - __bfloat162float(hi));
    A[(size_t)row * 512 + col] = hi;
    A[(size_t)row * 512 + 256 + col] = lo;
}

// ---------------------------------------------------------------------------
// Fused: agg = accum / max(norm,1e-8), split to bf16 hi/lo
// ---------------------------------------------------------------------------
__global__ void split_agg(const float* __restrict__ acc, const float* __restrict__ nrm,
                          __nv_bfloat16* __restrict__ A) {
    size_t i = (size_t)blockIdx.x * 256 + threadIdx.x;
    int row = (int)(i >> 8), col = (int)(i & 255);
    float v = acc[i] / fmaxf(nrm[row], 1e-8f);
    __nv_bfloat16 hi = __float2bfloat16(v);
    __nv_bfloat16 lo = __float2bfloat16(v - __bfloat162float(hi));
    A[(size_t)row * 512 + col] = hi;
    A[(size_t)row * 512 + 256 + col] = lo;
}

// ---------------------------------------------------------------------------
// Zero accumulators + norms
// ---------------------------------------------------------------------------
__global__ void zero_kernel(float* __restrict__ acc2, float* __restrict__ nrm) {
    size_t i = (size_t)blockIdx.x * blockDim.x + threadIdx.x;
    if (i < 2ull * NB) acc2[i] = 0.0f;
    if (i < 2 * NNODES) nrm[i] = 0.0f;
}

// ---------------------------------------------------------------------------
// Edge kernel: one warp per edge
// ---------------------------------------------------------------------------
__global__ void __launch_bounds__(256) edge_kernel(
    const float* __restrict__ qR, const float* __restrict__ Ksrc,
    const float* __restrict__ Vsrc, const int* __restrict__ ei,
    float* __restrict__ accum, float* __restrict__ nrm)
{
    const int lane = threadIdx.x & 31;
    const int warp = (blockIdx.x * blockDim.x + threadIdx.x) >> 5;
    const int nwarps = (gridDim.x * blockDim.x) >> 5;

    for (int e = warp; e < NEDGE; e += nwarps) {
        int src = ei[e];
        int dst = ei[NEDGE + e];
        const float* qrow = qR + (size_t)dst * 256;
        const float* krow = Ksrc + (size_t)src * 256;

        float aexp[NHEAD];
        float asum = 0.0f;
#pragma unroll
        for (int h = 0; h < NHEAD; h++) {
            float p = qrow[h * 32 + lane] * krow[h * 32 + lane];
#pragma unroll
            for (int o = 16; o; o >>= 1)
                p += __shfl_xor_sync(0xffffffffu, p, o);
            float s = p * 0.17677669529663687f;
            s = fminf(fmaxf(s, -5.0f), 5.0f);
            float a = expf(s);
            aexp[h] = a;
            asum += a;
        }

        const float* vrow = Vsrc + (size_t)src * 256;
        float* arow = accum + (size_t)dst * 256;
#pragma unroll
        for (int h = 0; h < NHEAD; h++)
            atomicAdd(&arow[h * 32 + lane], vrow[h * 32 + lane] * aexp[h]);

        if (lane == 0)
            atomicAdd(&nrm[dst], asum * 0.125f);
    }
}

// ---------------------------------------------------------------------------
__global__ void __launch_bounds__(256) ln_kernel(
    const float* __restrict__ in, const float* __restrict__ g,
    const float* __restrict__ be, float* __restrict__ out)
{
    const int warp = (blockIdx.x * blockDim.x + threadIdx.x) >> 5;
    const int lane = threadIdx.x & 31;
    if (warp >= NNODES) return;

    const float* row = in + (size_t)warp * 256;
    float v[8];
    float s = 0.0f;
#pragma unroll
    for (int j = 0; j < 8; j++) { v[j] = row[lane + j * 32]; s += v[j]; }
#pragma unroll
    for (int o = 16; o; o >>= 1) s += __shfl_xor_sync(0xffffffffu, s, o);
    float m = s * (1.0f / 256.0f);

    float q = 0.0f;
#pragma unroll
    for (int j = 0; j < 8; j++) { float d = v[j] - m; q += d * d; }
#pragma unroll
    for (int o = 16; o; o >>= 1) q += __shfl_xor_sync(0xffffffffu, q, o);
    float rstd = rsqrtf(q * (1.0f / 256.0f) + 1e-5f);

    float* orow = out + (size_t)warp * 256;
#pragma unroll
    for (int j = 0; j < 8; j++) {
        int c = lane + j * 32;
        orow[c] = (v[j] - m) * rstd * g[c] + be[c];
    }
}

// ---------------------------------------------------------------------------
extern "C" void kernel_launch(void* const* d_in, const int* in_sizes, int n_in,
                              void* d_out, int out_size) {
    const float* x_p   = (const float*)d_in[0];
    const float* x_a   = (const float*)d_in[1];
    const float* Wk_p  = (const float*)d_in[2];
    const float* bk_p  = (const float*)d_in[3];
    const float* Wq_p  = (const float*)d_in[4];
    const float* bq_p  = (const float*)d_in[5];
    const float* Wv_p  = (const float*)d_in[6];
    const float* bv_p  = (const float*)d_in[7];
    const float* Wo_p  = (const float*)d_in[8];
    const float* bo_p  = (const float*)d_in[9];
    const float* g_p   = (const float*)d_in[10];
    const float* be_p  = (const float*)d_in[11];
    const float* Wk_a  = (const float*)d_in[12];
    const float* bk_a  = (const float*)d_in[13];
    const float* Wq_a  = (const float*)d_in[14];
    const float* bq_a  = (const float*)d_in[15];
    const float* Wv_a  = (const float*)d_in[16];
    const float* bv_a  = (const float*)d_in[17];
    const float* Wo_a  = (const float*)d_in[18];
    const float* bo_a  = (const float*)d_in[19];
    const float* g_a   = (const float*)d_in[20];
    const float* be_a  = (const float*)d_in[21];
    const float* R_w   = (const float*)d_in[22];
    const int*   ei_w  = (const int*)d_in[23];
    const float* R_c   = (const float*)d_in[24];
    const int*   ei_c  = (const int*)d_in[25];
    const float* R_wb  = (const float*)d_in[26];
    const int*   ei_wb = (const int*)d_in[27];
    float* out = (float*)d_out;

    float* buf = nullptr; float* nrm = nullptr;
    __nv_bfloat16* acat = nullptr; __nv_bfloat16* bcat = nullptr;
    float* qbias = nullptr;
    cudaGetSymbolAddress((void**)&buf, g_buf);
    cudaGetSymbolAddress((void**)&nrm, g_norm);
    cudaGetSymbolAddress((void**)&acat, g_acat);
    cudaGetSymbolAddress((void**)&bcat, g_bcat);
    cudaGetSymbolAddress((void**)&qbias, g_bias);

    cudaFuncSetAttribute(gemm_tc<false>, cudaFuncAttributeMaxDynamicSharedMemorySize, GEMM_SMEM);
    cudaFuncSetAttribute(gemm_tc<true>,  cudaFuncAttributeMaxDynamicSharedMemorySize, GEMM_SMEM);

    float* Kp   = buf + 0 * NB;
    float* Vp   = buf + 1 * NB;
    float* Ka   = buf + 2 * NB;
    float* Va   = buf + 3 * NB;
    float* qRw  = buf + 4 * NB;
    float* qRc  = buf + 5 * NB;
    float* qRwb = buf + 6 * NB;
    float* accp = buf + 7 * NB;
    float* acca = buf + 8 * NB;
    float* np_  = nrm;
    float* na_  = nrm + NNODES;

    __nv_bfloat16* A0 = acat;                          // paper split
    __nv_bfloat16* A1 = acat + (size_t)NNODES * 512;   // author split
#define BC(i) (bcat + (size_t)(i) * 256 * 768)

    // 1) zero accumulators + norms
    zero_kernel<<<200000, 256>>>(accp, nrm);

    // 2) weight prep (bf16 hi/lo split, k-contig; qR weights composed with R)
    prep_w<<<256, 256>>>(Wk_p, BC(0));
    prep_w<<<256, 256>>>(Wv_p, BC(1));
    prep_w<<<256, 256>>>(Wk_a, BC(2));
    prep_w<<<256, 256>>>(Wv_a, BC(3));
    prep_qr<<<257, 256>>>(Wq_p, bq_p, R_w,  BC(4), qbias + 0);
    prep_qr<<<257, 256>>>(Wq_p, bq_p, R_c,  BC(5), qbias + 256);
    prep_qr<<<257, 256>>>(Wq_a, bq_a, R_wb, BC(6), qbias + 512);
    prep_w<<<256, 256>>>(Wo_p, BC(7));
    prep_w<<<256, 256>>>(Wo_a, BC(8));

    // 3) split inputs to bf16 hi/lo
    split_x<<<NNODES, 256>>>(x_p, A0);
    split_x<<<NNODES, 256>>>(x_a, A1);

    // 4) tensor-core GEMMs: K,V and fused qR projections
    dim3 gg((NNODES + 127) / 128, 2);
    gemm_tc<false><<<gg, 256, GEMM_SMEM>>>(A0, BC(0), bk_p, nullptr, Kp, NNODES);
    gemm_tc<false><<<gg, 256, GEMM_SMEM>>>(A0, BC(1), bv_p, nullptr, Vp, NNODES);
    gemm_tc<false><<<gg, 256, GEMM_SMEM>>>(A1, BC(2), bk_a, nullptr, Ka, NNODES);
    gemm_tc<false><<<gg, 256, GEMM_SMEM>>>(A1, BC(3), bv_a, nullptr, Va, NNODES);
    gemm_tc<false><<<gg, 256, GEMM_SMEM>>>(A0, BC(4), qbias + 0,   nullptr, qRw,  NNODES);
    gemm_tc<false><<<gg, 256, GEMM_SMEM>>>(A0, BC(5), qbias + 256, nullptr, qRc,  NNODES);
    gemm_tc<false><<<gg, 256, GEMM_SMEM>>>(A1, BC(6), qbias + 512, nullptr, qRwb, NNODES);

    // 5) edge message passing
    edge_kernel<<<2048, 256>>>(qRw,  Ka, Va, ei_w,  accp, np_);  // writes: author->paper
    edge_kernel<<<2048, 256>>>(qRc,  Kp, Vp, ei_c,  accp, np_);  // cites: paper->paper
    edge_kernel<<<2048, 256>>>(qRwb, Kp, Vp, ei_wb, acca, na_);  // writtenby: paper->author

    // 6) normalize + split aggregates (fused)
    split_agg<<<NNODES, 256>>>(accp, np_, A0);
    split_agg<<<NNODES, 256>>>(acca, na_, A1);

    // 7) output projection + residual (into recycled qR slabs)
    gemm_tc<true><<<gg, 256, GEMM_SMEM>>>(A0, BC(7), bo_p, x_p, qRw, NNODES);
    gemm_tc<true><<<gg, 256, GEMM_SMEM>>>(A1, BC(8), bo_a, x_a, qRc, NNODES);

    // 8) layernorm -> output [2, N, 256]
    ln_kernel<<<(NNODES * 32 + 255) / 256, 256>>>(qRw, g_p, be_p, out);
    ln_kernel<<<(NNODES * 32 + 255) / 256, 256>>>(qRc, g_a, be_a, out + (size_t)NNODES * 256);
}